// round 16
// baseline (speedup 1.0000x reference)
#include <cuda_runtime.h>
#include <cuda_fp16.h>
#include <math.h>
#include <stdint.h>

#define B_    32
#define L_    1024
#define CIN_  64
#define D_    512
#define DFF_  2048
#define NL_   3
#define TOPK_ 6
#define MROWS (B_*L_)   /* 32768 */

// ---------------- scratch (device globals; allocation-free) ----------------
__device__ float  g_h  [MROWS*D_];
__device__ float  g_h2 [MROWS*D_];
__device__ float  g_hn [MROWS*D_];
__device__ float  g_a  [MROWS*D_];
__device__ __half g_th [MROWS*D_];      // fp16 t (wo/ffn2 outputs, tf32-rounded bits)
__device__ __half g_qkvh[MROWS*3*D_];   // fused q|k|v fp16 (tf32-compatible bits), row stride 1536
__device__ float  g_ffn[MROWS*DFF_];    // fp32 ffn (layers 0,1)
__device__ __half g_ffnh[MROWS*DFF_];   // fp16 ffn (layer 2)
__device__ __half g_ah [MROWS*D_];      // fp16 agg out (layer 2)
__device__ __half g_h2h[MROWS*D_];      // fp16 h2 (layer 2)
__device__ __half g_hnh[MROWS*D_];      // fp16 ln out
__device__ float  g_xcat[MROWS*3*CIN_];
__device__ float2 g_Spart[B_*32*L_];
__device__ float  g_corr[B_*L_];
__device__ float  g_tcw [B_*TOPK_];
__device__ int    g_dly [B_*TOPK_];
__device__ float  g_cm  [B_*D_];
__device__ float  g_cb  [B_*CIN_];
// transposed (N,K) weights: tf32-rounded fp32 (pre-topk) / fp16 (post-topk)
__device__ float  g_wqkv[NL_*3*D_*D_];
__device__ float  g_bqkv[NL_*3*D_];
__device__ float  g_wto[NL_*D_*D_];     // l=0,1 used
__device__ float  g_wt1[NL_*DFF_*D_];   // l=0,1 used
__device__ float  g_wt2[NL_*D_*DFF_];   // l=0,1 used
__device__ float  g_wte[D_*192];
__device__ __half g_wtoh[D_*D_];        // layer-2 fp16 weights
__device__ __half g_wt1h[DFF_*D_];
__device__ __half g_wt2h[D_*DFF_];
__device__ __half g_wtph[128*D_];       // (64,512) padded to 128 rows

// ---------------- helpers ----------------
__device__ __forceinline__ float rtf32(float x) {
    uint32_t b = __float_as_uint(x);
    b = (b + 0x1000u) & 0xffffe000u;
    return __uint_as_float(b);
}
__device__ __forceinline__ float2 cadd(float2 a, float2 b){ return make_float2(a.x+b.x, a.y+b.y); }
__device__ __forceinline__ float2 csub(float2 a, float2 b){ return make_float2(a.x-b.x, a.y-b.y); }
__device__ __forceinline__ float2 cmul(float2 a, float2 b){ return make_float2(a.x*b.x-a.y*b.y, a.x*b.y+a.y*b.x); }
__device__ __forceinline__ float2 cneg(float2 a){ return make_float2(-a.x, -a.y); }

__device__ __forceinline__ uint32_t smem_u32(const void* p){
    uint32_t a;
    asm("{ .reg .u64 t; cvta.to.shared.u64 t, %1; cvt.u32.u64 %0, t; }" : "=r"(a) : "l"(p));
    return a;
}
__device__ __forceinline__ void cp16(uint32_t s, const void* g){
    asm volatile("cp.async.cg.shared.global [%0], [%1], 16;" :: "r"(s), "l"(g));
}
__device__ __forceinline__ void ldsm4(uint32_t* r, uint32_t addr){
    asm volatile("ldmatrix.sync.aligned.m8n8.x4.shared.b16 {%0,%1,%2,%3}, [%4];"
        : "=r"(r[0]),"=r"(r[1]),"=r"(r[2]),"=r"(r[3]) : "r"(addr));
}
#define MMA_TF32(d, a, b0, b1) \
    asm volatile("mma.sync.aligned.m16n8k8.row.col.f32.tf32.tf32.f32 " \
        "{%0,%1,%2,%3},{%4,%5,%6,%7},{%8,%9},{%0,%1,%2,%3};" \
        : "+f"((d)[0]),"+f"((d)[1]),"+f"((d)[2]),"+f"((d)[3]) \
        : "r"((a)[0]),"r"((a)[1]),"r"((a)[2]),"r"((a)[3]), "r"(b0),"r"(b1))
#define MMA_F16(d, a, b0, b1) \
    asm volatile("mma.sync.aligned.m16n8k16.row.col.f32.f16.f16.f32 " \
        "{%0,%1,%2,%3},{%4,%5,%6,%7},{%8,%9},{%0,%1,%2,%3};" \
        : "+f"((d)[0]),"+f"((d)[1]),"+f"((d)[2]),"+f"((d)[3]) \
        : "r"((a)[0]),"r"((a)[1]),"r"((a)[2]),"r"((a)[3]), "r"(b0),"r"(b1))

// ---------------- fused weight transposes: one launch, fp32 or fp16 dst ------
#define NJOBS 20
struct TJobs {
    const float* src[NJOBS];
    void*        dst[NJOBS];
    int K[NJOBS], N[NJOBS], Npad[NJOBS], tilesX[NJOBS], ishalf[NJOBS];
    int cum[NJOBS + 1];
};

__global__ void transpose_all_kernel(TJobs jb)
{
    __shared__ float t[32][33];
    int bid = blockIdx.x;
    int m = 0;
    while (bid >= jb.cum[m + 1]) m++;
    int lid = bid - jb.cum[m];
    int tX = jb.tilesX[m];
    int nb = (lid % tX) << 5, kb = (lid / tX) << 5;
    int K = jb.K[m], N = jb.N[m], Npad = jb.Npad[m];
    const float* in = jb.src[m];
    int x = threadIdx.x, y = threadIdx.y;     // 32 x 8
#pragma unroll
    for (int i = 0; i < 32; i += 8) {
        int k = kb + y + i, n = nb + x;
        t[y + i][x] = (k < K && n < N) ? in[(size_t)k * N + n] : 0.f;
    }
    __syncthreads();
    if (jb.ishalf[m]) {
        __half* out = (__half*)jb.dst[m];
#pragma unroll
        for (int i = 0; i < 32; i += 8) {
            int n = nb + y + i, k = kb + x;
            if (n < Npad && k < K) out[(size_t)n * K + k] = __float2half_rn(t[x][y + i]);
        }
    } else {
        float* out = (float*)jb.dst[m];
#pragma unroll
        for (int i = 0; i < 32; i += 8) {
            int n = nb + y + i, k = kb + x;
            if (n < Npad && k < K) out[(size_t)n * K + k] = rtf32(t[x][y + i]);
        }
    }
}

__global__ void biaspack_kernel(const float* __restrict__ bq, const float* __restrict__ bk,
                                const float* __restrict__ bv, float* __restrict__ out)
{
    int i = blockIdx.x*blockDim.x + threadIdx.x;
    if (i >= NL_*1536) return;
    int l = i / 1536, c = i % 1536;
    float v = (c < 512) ? bq[l*512 + c] : (c < 1024 ? bk[l*512 + c - 512] : bv[l*512 + c - 1024]);
    out[i] = v;
}

__global__ void xcat_kernel(const float* __restrict__ x, float* __restrict__ xc)
{
    int idx = blockIdx.x*blockDim.x + threadIdx.x;
    if (idx >= MROWS*192) return;
    int row = idx / 192, cc = idx % 192;
    int j = cc >> 6, c = cc & 63;
    int b = row >> 10, l = row & 1023;
    int ls = (l + j + 1023) & 1023;
    xc[idx] = rtf32(x[((((size_t)b)<<10) + ls)*64 + c]);
}

// ---------------- tf32 mma.sync GEMM (pre-topk path, bit-stable) -------------
template<int GELU, int ROUND>
__global__ __launch_bounds__(256, 2)
void tgemm(const float* __restrict__ A, const float* __restrict__ WT,
           const float* __restrict__ bias, float* __restrict__ Cf,
           __half* __restrict__ Ch, int K, int N)
{
    constexpr int STG_B = 32768;
    extern __shared__ float sm[];
    int tid = threadIdx.x;
    int lane = tid & 31, wid = tid >> 5;
    int wm = wid & 1, wn = wid >> 1;
    int bx = blockIdx.x, by = blockIdx.y;

    const float* Ab = A  + (size_t)(by * 128) * (size_t)K;
    const float* Bb = WT + (size_t)(bx * 128) * (size_t)K;
    const int nck = K >> 5;

    uint32_t sbase = smem_u32(sm);

    auto load = [&](int ck, int s){
        const float* ap = Ab + ck * 32;
        const float* bp = Bb + ck * 32;
        uint32_t st  = sbase + (uint32_t)s * STG_B;
        uint32_t st2 = st + 16384;
#pragma unroll
        for (int i = 0; i < 4; i++) {
            int t = tid + i*256;
            int row = t >> 3, ch = t & 7;
            uint32_t off = (uint32_t)((row << 7) + ((ch ^ (row & 7)) << 4));
            cp16(st + off, ap + (size_t)row*K + (ch << 2));
        }
#pragma unroll
        for (int i = 0; i < 4; i++) {
            int t = tid + i*256;
            int row = t >> 3, ch = t & 7;
            uint32_t off = (uint32_t)((row << 7) + ((ch ^ (row & 7)) << 4));
            cp16(st2 + off, bp + (size_t)row*K + (ch << 2));
        }
        asm volatile("cp.async.commit_group;" ::: "memory");
    };

    float acc[4][4][4];
#pragma unroll
    for (int mt = 0; mt < 4; mt++)
#pragma unroll
        for (int nt = 0; nt < 4; nt++)
#pragma unroll
            for (int j = 0; j < 4; j++) acc[mt][nt][j] = 0.f;

    int g = lane >> 3, r8 = lane & 7;
    int rA[4], rB[2];
#pragma unroll
    for (int mt = 0; mt < 4; mt++) rA[mt] = wm*64 + mt*16 + (g & 1)*8 + r8;
#pragma unroll
    for (int p = 0; p < 2; p++)    rB[p]  = wn*32 + p*16 + (g >> 1)*8 + r8;
    int chA = g >> 1;
    int chB = g & 1;

    load(0, 0); load(1, 1);
    int s = 0;

    for (int ck = 0; ck < nck; ck++) {
        asm volatile("cp.async.wait_group 1;" ::: "memory");
        __syncthreads();
        if (ck + 2 < nck) load(ck + 2, (s + 2 >= 3) ? s - 1 : s + 2);
        else asm volatile("cp.async.commit_group;" ::: "memory");

        uint32_t sa = sbase + (uint32_t)s * STG_B;
        uint32_t sb = sa + 16384;
#pragma unroll
        for (int kk = 0; kk < 4; kk++) {
            uint32_t af[4][4], bf[2][4];
#pragma unroll
            for (int mt = 0; mt < 4; mt++) {
                int ch = 2*kk + chA;
                uint32_t off = (uint32_t)((rA[mt] << 7) + ((ch ^ (rA[mt] & 7)) << 4));
                ldsm4(af[mt], sa + off);
            }
#pragma unroll
            for (int p = 0; p < 2; p++) {
                int ch = 2*kk + chB;
                uint32_t off = (uint32_t)((rB[p] << 7) + ((ch ^ (rB[p] & 7)) << 4));
                ldsm4(bf[p], sb + off);
            }
#pragma unroll
            for (int mt = 0; mt < 4; mt++)
#pragma unroll
                for (int nt = 0; nt < 4; nt++) {
                    int p = nt >> 1, q = nt & 1;
                    MMA_TF32(acc[mt][nt], af[mt], bf[p][2*q], bf[p][2*q+1]);
                }
        }
        s = (s == 2) ? 0 : s + 1;
    }

#pragma unroll
    for (int mt = 0; mt < 4; mt++) {
        int r0 = by*128 + wm*64 + mt*16 + (lane >> 2);
#pragma unroll
        for (int nt = 0; nt < 4; nt++) {
            int c = bx*128 + wn*32 + nt*8 + ((lane & 3) << 1);
            if (c < N) {
                float v0 = acc[mt][nt][0], v1 = acc[mt][nt][1];
                float v2 = acc[mt][nt][2], v3 = acc[mt][nt][3];
                if (bias != nullptr) {
                    float b0c = bias[c], b1c = bias[c+1];
                    v0 += b0c; v1 += b1c; v2 += b0c; v3 += b1c;
                }
                if (GELU) {
                    v0 = 0.5f*v0*(1.f + erff(v0*0.7071067811865475f));
                    v1 = 0.5f*v1*(1.f + erff(v1*0.7071067811865475f));
                    v2 = 0.5f*v2*(1.f + erff(v2*0.7071067811865475f));
                    v3 = 0.5f*v3*(1.f + erff(v3*0.7071067811865475f));
                }
                if (ROUND) { v0 = rtf32(v0); v1 = rtf32(v1); v2 = rtf32(v2); v3 = rtf32(v3); }
                if (Cf != nullptr) {
                    float* row0 = Cf + (size_t)r0 * (size_t)N;
                    float* row1 = row0 + ((size_t)N << 3);
                    *(float2*)(row0 + c) = make_float2(v0, v1);
                    *(float2*)(row1 + c) = make_float2(v2, v3);
                }
                if (Ch != nullptr) {
                    __half* hrow0 = Ch + (size_t)r0 * (size_t)N;
                    __half* hrow1 = hrow0 + ((size_t)N << 3);
                    *(__half2*)(hrow0 + c) = __halves2half2(__float2half_rn(v0), __float2half_rn(v1));
                    *(__half2*)(hrow1 + c) = __halves2half2(__float2half_rn(v2), __float2half_rn(v3));
                }
            }
        }
    }
}

// ---------------- fp16 mma.sync GEMM (post-last-topk path, 2x rate) ----------
template<int GELU>
__global__ __launch_bounds__(256, 2)
void tgemm_h(const __half* __restrict__ A, const __half* __restrict__ WT,
             const float* __restrict__ bias, float* __restrict__ Cf,
             __half* __restrict__ Ch, int K, int N)
{
    constexpr int STG_B = 32768;
    extern __shared__ float sm[];
    int tid = threadIdx.x;
    int lane = tid & 31, wid = tid >> 5;
    int wm = wid & 1, wn = wid >> 1;
    int bx = blockIdx.x, by = blockIdx.y;

    const __half* Ab = A  + (size_t)(by * 128) * (size_t)K;
    const __half* Bb = WT + (size_t)(bx * 128) * (size_t)K;
    const int nck = K >> 6;

    uint32_t sbase = smem_u32(sm);

    auto load = [&](int ck, int s){
        const __half* ap = Ab + ck * 64;
        const __half* bp = Bb + ck * 64;
        uint32_t st  = sbase + (uint32_t)s * STG_B;
        uint32_t st2 = st + 16384;
#pragma unroll
        for (int i = 0; i < 4; i++) {
            int t = tid + i*256;
            int row = t >> 3, ch = t & 7;
            uint32_t off = (uint32_t)((row << 7) + ((ch ^ (row & 7)) << 4));
            cp16(st + off, ap + (size_t)row*K + (ch << 3));
        }
#pragma unroll
        for (int i = 0; i < 4; i++) {
            int t = tid + i*256;
            int row = t >> 3, ch = t & 7;
            uint32_t off = (uint32_t)((row << 7) + ((ch ^ (row & 7)) << 4));
            cp16(st2 + off, bp + (size_t)row*K + (ch << 3));
        }
        asm volatile("cp.async.commit_group;" ::: "memory");
    };

    float acc[4][4][4];
#pragma unroll
    for (int mt = 0; mt < 4; mt++)
#pragma unroll
        for (int nt = 0; nt < 4; nt++)
#pragma unroll
            for (int j = 0; j < 4; j++) acc[mt][nt][j] = 0.f;

    int g = lane >> 3, r8 = lane & 7;
    int rA[4], rB[2];
#pragma unroll
    for (int mt = 0; mt < 4; mt++) rA[mt] = wm*64 + mt*16 + (g & 1)*8 + r8;
#pragma unroll
    for (int p = 0; p < 2; p++)    rB[p]  = wn*32 + p*16 + (g >> 1)*8 + r8;
    int chA = g >> 1;
    int chB = g & 1;

    load(0, 0); load(1, 1);
    int s = 0;

    for (int ck = 0; ck < nck; ck++) {
        asm volatile("cp.async.wait_group 1;" ::: "memory");
        __syncthreads();
        if (ck + 2 < nck) load(ck + 2, (s + 2 >= 3) ? s - 1 : s + 2);
        else asm volatile("cp.async.commit_group;" ::: "memory");

        uint32_t sa = sbase + (uint32_t)s * STG_B;
        uint32_t sb = sa + 16384;
#pragma unroll
        for (int kk = 0; kk < 4; kk++) {
            uint32_t af[4][4], bf[2][4];
#pragma unroll
            for (int mt = 0; mt < 4; mt++) {
                int ch = 2*kk + chA;
                uint32_t off = (uint32_t)((rA[mt] << 7) + ((ch ^ (rA[mt] & 7)) << 4));
                ldsm4(af[mt], sa + off);
            }
#pragma unroll
            for (int p = 0; p < 2; p++) {
                int ch = 2*kk + chB;
                uint32_t off = (uint32_t)((rB[p] << 7) + ((ch ^ (rB[p] & 7)) << 4));
                ldsm4(bf[p], sb + off);
            }
#pragma unroll
            for (int mt = 0; mt < 4; mt++)
#pragma unroll
                for (int nt = 0; nt < 4; nt++) {
                    int p = nt >> 1, q = nt & 1;
                    MMA_F16(acc[mt][nt], af[mt], bf[p][2*q], bf[p][2*q+1]);
                }
        }
        s = (s == 2) ? 0 : s + 1;
    }

#pragma unroll
    for (int mt = 0; mt < 4; mt++) {
        int r0 = by*128 + wm*64 + mt*16 + (lane >> 2);
#pragma unroll
        for (int nt = 0; nt < 4; nt++) {
            int c = bx*128 + wn*32 + nt*8 + ((lane & 3) << 1);
            if (c < N) {
                float v0 = acc[mt][nt][0], v1 = acc[mt][nt][1];
                float v2 = acc[mt][nt][2], v3 = acc[mt][nt][3];
                if (bias != nullptr) {
                    float b0c = bias[c], b1c = bias[c+1];
                    v0 += b0c; v1 += b1c; v2 += b0c; v3 += b1c;
                }
                if (GELU) {
                    v0 = 0.5f*v0*(1.f + erff(v0*0.7071067811865475f));
                    v1 = 0.5f*v1*(1.f + erff(v1*0.7071067811865475f));
                    v2 = 0.5f*v2*(1.f + erff(v2*0.7071067811865475f));
                    v3 = 0.5f*v3*(1.f + erff(v3*0.7071067811865475f));
                }
                if (Cf != nullptr) {
                    float* row0 = Cf + (size_t)r0 * (size_t)N;
                    float* row1 = row0 + ((size_t)N << 3);
                    *(float2*)(row0 + c) = make_float2(v0, v1);
                    *(float2*)(row1 + c) = make_float2(v2, v3);
                }
                if (Ch != nullptr) {
                    __half* hrow0 = Ch + (size_t)r0 * (size_t)N;
                    __half* hrow1 = hrow0 + ((size_t)N << 3);
                    *(__half2*)(hrow0 + c) = __halves2half2(__float2half_rn(v0), __float2half_rn(v1));
                    *(__half2*)(hrow1 + c) = __halves2half2(__float2half_rn(v2), __float2half_rn(v3));
                }
            }
        }
    }
}

// ---------------- radix-4 FFT helpers ----------------
template<int INV>
__device__ __forceinline__ float2 twget(const float2* tw, int e)
{
    float2 w = (e < 512) ? tw[e] : cneg(tw[e - 512]);
    if (INV) w.y = -w.y;
    return w;
}

template<int INV>
__device__ void fft1024_r4(float2* z, const float2* tw)
{
    int tid = threadIdx.x;   // 256-thread version (ifft)
#pragma unroll
    for (int q = 1; q <= 256; q <<= 2) {
        int step = 256 / q;
        int j = tid & (q - 1);
        int base = ((tid & ~(q - 1)) << 2) + j;
        float2 x0 = z[base];
        float2 x1 = cmul(twget<INV>(tw, j*step),   z[base + q]);
        float2 x2 = cmul(twget<INV>(tw, 2*j*step), z[base + 2*q]);
        float2 x3 = cmul(twget<INV>(tw, 3*j*step), z[base + 3*q]);
        float2 t0 = cadd(x0, x2), t1 = csub(x0, x2);
        float2 t2 = cadd(x1, x3);
        float2 d  = csub(x1, x3);
        float2 t3 = INV ? make_float2(-d.y, d.x) : make_float2(d.y, -d.x);
        z[base]       = cadd(t0, t2);
        z[base + q]   = cadd(t1, t3);
        z[base + 2*q] = csub(t0, t2);
        z[base + 3*q] = csub(t1, t3);
        __syncthreads();
    }
}

__device__ __forceinline__ int r4rev(int t)
{
    int r = 0;
#pragma unroll
    for (int i = 0; i < 5; i++) { r = (r << 2) | (t & 3); t >>= 2; }
    return r;
}

// 512 threads: two channels' FFTs in flight (warps 0-7 -> z0, 8-15 -> z1)
__global__ __launch_bounds__(512)
void corr_fft_kernel(const __half* __restrict__ qkv, float2* __restrict__ Spart)
{
    __shared__ float2 z0[1024];
    __shared__ float2 z1[1024];
    __shared__ float2 acc[1024];
    __shared__ float2 tw[512];
    int tid = threadIdx.x;
    int b = blockIdx.x, g = blockIdx.y;

    if (tid < 512) {
        float s, c;
        sincosf(-6.283185307179586f * (float)tid / 1024.f, &s, &c);
        tw[tid] = make_float2(c, s);
    }
    for (int i = tid; i < 1024; i += 512) acc[i] = make_float2(0.f, 0.f);
    __syncthreads();

    const __half* qb = qkv + (((size_t)b) << 10) * 1536;

    for (int it = 0; it < 8; it++) {
        int d = (g << 4) + (it << 1);
        for (int t = tid; t < 1024; t += 512) {
            const __half* rp = qb + (size_t)t * 1536 + d;
            float2 qf = __half22float2(*(const __half2*)(rp));
            float2 kf = __half22float2(*(const __half2*)(rp + 512));
            int r = r4rev(t);
            z0[r] = make_float2(qf.x, kf.x);
            z1[r] = make_float2(qf.y, kf.y);
        }
        __syncthreads();
        {
            float2* zz = (tid < 256) ? z0 : z1;   // uniform per warp
            int t5 = tid & 255;
#pragma unroll
            for (int q = 1; q <= 256; q <<= 2) {
                int step = 256 / q;
                int j = t5 & (q - 1);
                int base = ((t5 & ~(q - 1)) << 2) + j;
                float2 x0 = zz[base];
                float2 x1 = cmul(twget<0>(tw, j*step),   zz[base + q]);
                float2 x2 = cmul(twget<0>(tw, 2*j*step), zz[base + 2*q]);
                float2 x3 = cmul(twget<0>(tw, 3*j*step), zz[base + 3*q]);
                float2 t0 = cadd(x0, x2), t1 = csub(x0, x2);
                float2 t2 = cadd(x1, x3);
                float2 dd = csub(x1, x3);
                float2 t3 = make_float2(dd.y, -dd.x);
                zz[base]       = cadd(t0, t2);
                zz[base + q]   = cadd(t1, t3);
                zz[base + 2*q] = csub(t0, t2);
                zz[base + 3*q] = csub(t1, t3);
                __syncthreads();
            }
        }
        for (int f = tid; f < 1024; f += 512) {
            int fm = (1024 - f) & 1023;
            float2 Zf = z0[f], Zm = z0[fm];
            float Qx = 0.5f*(Zf.x + Zm.x), Qy = 0.5f*(Zf.y - Zm.y);
            float Kx = 0.5f*(Zf.y + Zm.y), Ky = 0.5f*(Zm.x - Zf.x);
            float2 P0 = make_float2(Qx*Kx + Qy*Ky, Qy*Kx - Qx*Ky);
            float2 Yf = z1[f], Ym = z1[fm];
            float qx = 0.5f*(Yf.x + Ym.x), qy = 0.5f*(Yf.y - Ym.y);
            float kx = 0.5f*(Yf.y + Ym.y), ky = 0.5f*(Ym.x - Yf.x);
            float2 P1 = make_float2(qx*kx + qy*ky, qy*kx - qx*ky);
            acc[f] = cadd(acc[f], cadd(P0, P1));
        }
        __syncthreads();
    }
    float2* outp = Spart + ((((size_t)b) << 5) + g) * 1024;
    for (int f = tid; f < 1024; f += 512) outp[f] = acc[f];
}

__global__ __launch_bounds__(256)
void corr_ifft_kernel(const float2* __restrict__ Spart, float* __restrict__ corr)
{
    __shared__ float2 z[1024];
    __shared__ float2 tw[512];
    int tid = threadIdx.x;
    int b = blockIdx.x;

    for (int i = tid; i < 512; i += 256) {
        float s, c;
        sincosf(-6.283185307179586f * (float)i / 1024.f, &s, &c);
        tw[i] = make_float2(c, s);
    }
    __syncthreads();
    for (int t = tid; t < 1024; t += 256) {
        float2 s = make_float2(0.f, 0.f);
        const float2* sp = Spart + ((((size_t)b) << 5) * 1024) + t;
        for (int g2 = 0; g2 < 32; g2++) s = cadd(s, sp[(size_t)g2 << 10]);
        z[r4rev(t)] = s;
    }
    __syncthreads();
    fft1024_r4<1>(z, tw);
    const float scale = 1.f / (1024.f * 512.f);
    for (int t = tid; t < 1024; t += 256)
        corr[(b << 10) + t] = z[t].x * scale;
}

__global__ __launch_bounds__(256)
void topk_kernel(const float* __restrict__ corr, float* __restrict__ tcw, int* __restrict__ dly)
{
    int b = blockIdx.x, t = threadIdx.x;
    __shared__ float vals[1024];
    __shared__ float rv[256];
    __shared__ int   ri[256];
    __shared__ float wv[TOPK_];
    __shared__ int   wi[TOPK_];
    for (int i = t; i < 1024; i += 256) vals[i] = corr[(b << 10) + i];
    __syncthreads();
    for (int kk = 0; kk < TOPK_; kk++) {
        float bm = -INFINITY; int bi = 0x7fffffff;
        for (int i = t; i < 1024; i += 256) {
            float v = vals[i];
            if (v > bm || (v == bm && i < bi)) { bm = v; bi = i; }
        }
        rv[t] = bm; ri[t] = bi;
        __syncthreads();
        for (int s = 128; s > 0; s >>= 1) {
            if (t < s) {
                if (rv[t+s] > rv[t] || (rv[t+s] == rv[t] && ri[t+s] < ri[t])) {
                    rv[t] = rv[t+s]; ri[t] = ri[t+s];
                }
            }
            __syncthreads();
        }
        if (t == 0) { wv[kk] = rv[0]; wi[kk] = ri[0]; vals[ri[0]] = -INFINITY; }
        __syncthreads();
    }
    if (t == 0) {
        float m = wv[0];
        for (int kk = 1; kk < TOPK_; kk++) m = fmaxf(m, wv[kk]);
        float e[TOPK_], s = 0.f;
        for (int kk = 0; kk < TOPK_; kk++) { e[kk] = expf(wv[kk] - m); s += e[kk]; }
        float inv = 1.f / s;
        for (int kk = 0; kk < TOPK_; kk++) {
            tcw[b*TOPK_ + kk] = e[kk] * inv;
            dly[b*TOPK_ + kk] = wi[kk];
        }
    }
}

__global__ __launch_bounds__(128)
void agg_kernel(const __half* __restrict__ qkv, const float* __restrict__ tcw,
                const int* __restrict__ dly, float* __restrict__ outp,
                __half* __restrict__ outh)
{
    int bl = blockIdx.x;
    int b = bl >> 10, l = bl & 1023;
    __shared__ float w[TOPK_];
    __shared__ int   dd[TOPK_];
    if (threadIdx.x < TOPK_) {
        w[threadIdx.x]  = tcw[b*TOPK_ + threadIdx.x];
        dd[threadIdx.x] = dly[b*TOPK_ + threadIdx.x];
    }
    __syncthreads();
    int c = threadIdx.x << 2;
    float4 acc = make_float4(0.f, 0.f, 0.f, 0.f);
#pragma unroll
    for (int kk = 0; kk < TOPK_; kk++) {
        int row = (l + dd[kk]) & 1023;
        const __half* vp = qkv + ((((size_t)b) << 10) + row) * 1536 + 1024 + c;
        __half2 p0 = *(const __half2*)(vp);
        __half2 p1 = *(const __half2*)(vp + 2);
        float2 f0 = __half22float2(p0), f1 = __half22float2(p1);
        acc.x = fmaf(w[kk], f0.x, acc.x);
        acc.y = fmaf(w[kk], f0.y, acc.y);
        acc.z = fmaf(w[kk], f1.x, acc.z);
        acc.w = fmaf(w[kk], f1.y, acc.w);
    }
    acc.x = rtf32(acc.x); acc.y = rtf32(acc.y); acc.z = rtf32(acc.z); acc.w = rtf32(acc.w);
    if (outp != nullptr)
        *(float4*)(outp + (((size_t)bl) << 9) + c) = acc;
    if (outh != nullptr) {
        __half* op = outh + (((size_t)bl) << 9) + c;
        *(__half2*)(op)     = __halves2half2(__float2half_rn(acc.x), __float2half_rn(acc.y));
        *(__half2*)(op + 2) = __halves2half2(__float2half_rn(acc.z), __float2half_rn(acc.w));
    }
}

// decomp: in1 fp32 + in2 fp16 (tf32-rounded bits); fp32 out + optional fp16 shadow
__global__ __launch_bounds__(256)
void decomp_kernel(const float* __restrict__ in1, const __half* __restrict__ in2,
                   float* __restrict__ outp, __half* __restrict__ outh)
{
    __shared__ float s[152][64];
    int b = blockIdx.x, lt = blockIdx.y, dt = blockIdx.z;
    int l0 = lt << 7, d0 = dt << 6;
    int tid = threadIdx.x;
    for (int i = tid; i < 152*64; i += 256) {
        int r = i >> 6, d = i & 63;
        int l = l0 - 12 + r;
        l = l < 0 ? 0 : (l > 1023 ? 1023 : l);
        size_t gi = (((((size_t)b) << 10) + l) << 9) + d0 + d;
        s[r][d] = in1[gi] + __half2float(in2[gi]);
    }
    __syncthreads();
    int d = tid & 63, ch = tid >> 6;
    int lb = ch << 5;
    float sum = 0.f;
#pragma unroll
    for (int j = 0; j < 25; j++) sum += s[lb + j][d];
    for (int i = 0; i < 32; i++) {
        size_t gi = (((((size_t)b) << 10) + (l0 + lb + i)) << 9) + d0 + d;
        float v = rtf32(s[lb + 12 + i][d] - sum * (1.f/25.f));
        outp[gi] = v;
        if (outh != nullptr) outh[gi] = __float2half_rn(v);
        if (i != 31) sum += s[lb + 25 + i][d] - s[lb + i][d];
    }
}

__global__ __launch_bounds__(128)
void ln_kernel(const float* __restrict__ h, const float* __restrict__ gam,
               const float* __restrict__ bet, float* __restrict__ hn,
               __half* __restrict__ hnh)
{
    int row = blockIdx.x;
    int t = threadIdx.x;
    const float4 x = *(const float4*)(h + (((size_t)row) << 9) + (t << 2));
    float s1 = x.x + x.y + x.z + x.w;
    float s2 = x.x*x.x + x.y*x.y + x.z*x.z + x.w*x.w;
#pragma unroll
    for (int o = 16; o > 0; o >>= 1) {
        s1 += __shfl_xor_sync(0xffffffffu, s1, o);
        s2 += __shfl_xor_sync(0xffffffffu, s2, o);
    }
    __shared__ float a1[4], a2[4];
    if ((t & 31) == 0) { a1[t >> 5] = s1; a2[t >> 5] = s2; }
    __syncthreads();
    s1 = a1[0] + a1[1] + a1[2] + a1[3];
    s2 = a2[0] + a2[1] + a2[2] + a2[3];
    float mu  = s1 * (1.f/512.f);
    float var = s2 * (1.f/512.f) - mu*mu;
    float rs  = rsqrtf(var + 1e-5f);
    int c = t << 2;
    float4 o4;
    o4.x = rtf32((x.x - mu)*rs*gam[c+0] + bet[c+0]);
    o4.y = rtf32((x.y - mu)*rs*gam[c+1] + bet[c+1]);
    o4.z = rtf32((x.z - mu)*rs*gam[c+2] + bet[c+2]);
    o4.w = rtf32((x.w - mu)*rs*gam[c+3] + bet[c+3]);
    *(float4*)(hn + (((size_t)row) << 9) + c) = o4;
    __half* hp = hnh + (((size_t)row) << 9) + c;
    *(__half2*)(hp)     = __halves2half2(__float2half_rn(o4.x), __float2half_rn(o4.y));
    *(__half2*)(hp + 2) = __halves2half2(__float2half_rn(o4.z), __float2half_rn(o4.w));
}

__global__ __launch_bounds__(128)
void colmean_kernel(const float* __restrict__ hn, float* __restrict__ cm)
{
    int b = blockIdx.x;
    int d = blockIdx.y * 128 + threadIdx.x;
    float s = 0.f;
    const float* p = hn + ((((size_t)b) << 10) << 9) + d;
    for (int l = 0; l < 1024; l++) s += p[((size_t)l) << 9];
    cm[(b << 9) + d] = s * (1.f/1024.f);
}

__global__ __launch_bounds__(64)
void cbias_kernel(const float* __restrict__ cm, const float* __restrict__ pw,
                  float* __restrict__ cb)
{
    int b = blockIdx.x, n = threadIdx.x;
    float s = 0.f;
    for (int d2 = 0; d2 < 512; d2++)
        s = fmaf(cm[(b << 9) + d2], __half2float(__float2half_rn(pw[d2*64 + n])), s);
    cb[(b << 6) + n] = s;
}

__global__ void sub_kernel(float* __restrict__ outp, const float* __restrict__ cb)
{
    int i = blockIdx.x * blockDim.x + threadIdx.x;
    if (i >= MROWS*64) return;
    outp[i] -= cb[((i >> 16) << 6) + (i & 63)];
}

// ---------------- host launcher ----------------
extern "C" void kernel_launch(void* const* d_in, const int* in_sizes, int n_in,
                              void* d_out, int out_size)
{
    const float* x       = (const float*)d_in[0];
    const float* embed_w = (const float*)d_in[1];
    const float* wq = (const float*)d_in[2];  const float* bq = (const float*)d_in[3];
    const float* wk = (const float*)d_in[4];  const float* bk = (const float*)d_in[5];
    const float* wv = (const float*)d_in[6];  const float* bv = (const float*)d_in[7];
    const float* wo = (const float*)d_in[8];  const float* bo = (const float*)d_in[9];
    const float* w1 = (const float*)d_in[10]; const float* w2 = (const float*)d_in[11];
    const float* ln_g = (const float*)d_in[12]; const float* ln_b = (const float*)d_in[13];
    const float* pw = (const float*)d_in[14]; const float* pb = (const float*)d_in[15];
    float* outp = (float*)d_out;
    (void)in_sizes; (void)n_in; (void)out_size;

    float *h, *h2, *hn, *a, *ffn, *xc, *corr, *tcw, *cm, *cb, *bqkv;
    float *wqkv, *wto, *wt1, *wt2, *wte;
    __half *th, *qkvh, *ffnh, *ah, *h2h, *hnh, *wtoh, *wt1h, *wt2h, *wtph;
    float2* sp; int* dly;
    cudaGetSymbolAddress((void**)&h,    g_h);
    cudaGetSymbolAddress((void**)&h2,   g_h2);
    cudaGetSymbolAddress((void**)&hn,   g_hn);
    cudaGetSymbolAddress((void**)&a,    g_a);
    cudaGetSymbolAddress((void**)&th,   g_th);
    cudaGetSymbolAddress((void**)&qkvh, g_qkvh);
    cudaGetSymbolAddress((void**)&ffn,  g_ffn);
    cudaGetSymbolAddress((void**)&ffnh, g_ffnh);
    cudaGetSymbolAddress((void**)&ah,   g_ah);
    cudaGetSymbolAddress((void**)&h2h,  g_h2h);
    cudaGetSymbolAddress((void**)&hnh,  g_hnh);
    cudaGetSymbolAddress((void**)&xc,   g_xcat);
    cudaGetSymbolAddress((void**)&sp,   g_Spart);
    cudaGetSymbolAddress((void**)&corr, g_corr);
    cudaGetSymbolAddress((void**)&tcw,  g_tcw);
    cudaGetSymbolAddress((void**)&dly,  g_dly);
    cudaGetSymbolAddress((void**)&cm,   g_cm);
    cudaGetSymbolAddress((void**)&cb,   g_cb);
    cudaGetSymbolAddress((void**)&wqkv, g_wqkv);
    cudaGetSymbolAddress((void**)&bqkv, g_bqkv);
    cudaGetSymbolAddress((void**)&wto,  g_wto);
    cudaGetSymbolAddress((void**)&wt1,  g_wt1);
    cudaGetSymbolAddress((void**)&wt2,  g_wt2);
    cudaGetSymbolAddress((void**)&wte,  g_wte);
    cudaGetSymbolAddress((void**)&wtoh, g_wtoh);
    cudaGetSymbolAddress((void**)&wt1h, g_wt1h);
    cudaGetSymbolAddress((void**)&wt2h, g_wt2h);
    cudaGetSymbolAddress((void**)&wtph, g_wtph);

    const int SMB = 3 * 32768;
    cudaFuncSetAttribute(tgemm<0,1>, cudaFuncAttributeMaxDynamicSharedMemorySize, SMB);
    cudaFuncSetAttribute(tgemm<1,1>, cudaFuncAttributeMaxDynamicSharedMemorySize, SMB);
    cudaFuncSetAttribute(tgemm<0,0>, cudaFuncAttributeMaxDynamicSharedMemorySize, SMB);
    cudaFuncSetAttribute(tgemm_h<0>, cudaFuncAttributeMaxDynamicSharedMemorySize, SMB);
    cudaFuncSetAttribute(tgemm_h<1>, cudaFuncAttributeMaxDynamicSharedMemorySize, SMB);

    // ---- fused transpose job table ----
    TJobs jb;
    int nj = 0, cum = 0;
    auto addjob = [&](const float* src, void* dst, int K, int N, int Npad, int ishalf) {
        jb.src[nj] = src; jb.dst[nj] = dst;
        jb.K[nj] = K; jb.N[nj] = N; jb.Npad[nj] = Npad; jb.ishalf[nj] = ishalf;
        int tx = (Npad + 31) / 32, ty = (K + 31) / 32;
        jb.tilesX[nj] = tx;
        jb.cum[nj] = cum;
        cum += tx * ty;
        nj++;
    };
    addjob(embed_w, wte,  192, 512, 512, 0);
    addjob(pw,      wtph, 512, 64, 128, 1);
    for (int l = 0; l < NL_; l++) {
        float* wl = wqkv + (size_t)l*1536*512;
        addjob(wq + (size_t)l*D_*D_,   wl,                    512, 512, 512, 0);
        addjob(wk + (size_t)l*D_*D_,   wl + (size_t)512*512,  512, 512, 512, 0);
        addjob(wv + (size_t)l*D_*D_,   wl + (size_t)1024*512, 512, 512, 512, 0);
        if (l < NL_ - 1) {
            addjob(wo + (size_t)l*D_*D_,   wto + (size_t)l*D_*D_,   512, 512, 512, 0);
            addjob(w1 + (size_t)l*D_*DFF_, wt1 + (size_t)l*D_*DFF_, 512, 2048, 2048, 0);
            addjob(w2 + (size_t)l*D_*DFF_, wt2 + (size_t)l*D_*DFF_, 2048, 512, 512, 0);
        } else {
            addjob(wo + (size_t)l*D_*D_,   wtoh, 512, 512, 512, 1);
            addjob(w1 + (size_t)l*D_*DFF_, wt1h, 512, 2048, 2048, 1);
            addjob(w2 + (size_t)l*D_*DFF_, wt2h, 2048, 512, 512, 1);
        }
    }
    jb.cum[nj] = cum;
    transpose_all_kernel<<<cum, dim3(32, 8)>>>(jb);
    biaspack_kernel<<<(NL_*1536 + 255)/256, 256>>>(bq, bk, bv, bqkv);

    dim3 g512 (4,  MROWS/128);
    dim3 g1536(12, MROWS/128);
    dim3 g2048(16, MROWS/128);
    dim3 g64  (1,  MROWS/128);

    xcat_kernel<<<(MROWS*192 + 255)/256, 256>>>(x, xc);
    tgemm<0,1><<<g512, 256, SMB>>>(xc, wte, nullptr, h, nullptr, 192, 512);

    for (int l = 0; l < NL_; l++) {
        tgemm<0,0><<<g1536, 256, SMB>>>(h, wqkv + (size_t)l*1536*512, bqkv + l*1536,
                                        nullptr, qkvh, 512, 1536);

        corr_fft_kernel <<<dim3(B_, 32), 512>>>(qkvh, sp);
        corr_ifft_kernel<<<B_, 256>>>(sp, corr);
        topk_kernel     <<<B_, 256>>>(corr, tcw, dly);

        if (l < NL_ - 1) {
            // pre-topk path: bit-stable tf32 (t stored fp16 = identical bits post-rtf32)
            agg_kernel<<<MROWS, 128>>>(qkvh, tcw, dly, a, nullptr);
            tgemm<0,1><<<g512, 256, SMB>>>(a, wto + (size_t)l*D_*D_, bo + l*D_, nullptr, th, 512, 512);
            decomp_kernel<<<dim3(B_, 8, 8), 256>>>(h, th, h2, nullptr);
            tgemm<1,1><<<g2048, 256, SMB>>>(h2, wt1 + (size_t)l*D_*DFF_, nullptr, ffn, nullptr, 512, 2048);
            tgemm<0,1><<<g512,  256, SMB>>>(ffn, wt2 + (size_t)l*D_*DFF_, nullptr, nullptr, th, 2048, 512);
            decomp_kernel<<<dim3(B_, 8, 8), 256>>>(h2, th, h, nullptr);
        } else {
            // post-last-topk path: fp16 MMA
            agg_kernel<<<MROWS, 128>>>(qkvh, tcw, dly, nullptr, ah);
            tgemm_h<0><<<g512, 256, SMB>>>(ah, wtoh, bo + l*D_, nullptr, th, 512, 512);
            decomp_kernel<<<dim3(B_, 8, 8), 256>>>(h, th, h2, h2h);
            tgemm_h<1><<<g2048, 256, SMB>>>(h2h, wt1h, nullptr, nullptr, ffnh, 512, 2048);
            tgemm_h<0><<<g512,  256, SMB>>>(ffnh, wt2h, nullptr, nullptr, th, 2048, 512);
            decomp_kernel<<<dim3(B_, 8, 8), 256>>>(h2, th, h, nullptr);
        }
    }

    ln_kernel<<<MROWS, 128>>>(h, ln_g, ln_b, hn, hnh);
    colmean_kernel<<<dim3(B_, 4), 128>>>(hn, cm);
    cbias_kernel<<<B_, 64>>>(cm, pw, cb);
    tgemm_h<0><<<g64, 256, SMB>>>(hnh, wtph, pb, outp, nullptr, 512, 64);
    sub_kernel<<<(MROWS*64 + 255)/256, 256>>>(outp, cb);
}

// round 17
// speedup vs baseline: 1.4723x; 1.4723x over previous
#include <cuda_runtime.h>
#include <cuda_fp16.h>
#include <math.h>
#include <stdint.h>

#define B_    32
#define L_    1024
#define CIN_  64
#define D_    512
#define DFF_  2048
#define NL_   3
#define TOPK_ 6
#define MROWS (B_*L_)   /* 32768 */

// ---------------- scratch (device globals; allocation-free) ----------------
__device__ float  g_h  [MROWS*D_];
__device__ float  g_h2 [MROWS*D_];
__device__ float  g_hn [MROWS*D_];
__device__ float  g_a  [MROWS*D_];
__device__ __half g_th [MROWS*D_];      // fp16 t (wo/ffn2 outputs, tf32-rounded bits)
__device__ __half g_qkvh[MROWS*3*D_];   // fused q|k|v fp16 (tf32-compatible bits), row stride 1536
__device__ float  g_ffn[MROWS*DFF_];    // fp32 ffn (layers 0,1)
__device__ __half g_ffnh[MROWS*DFF_];   // fp16 ffn (layer 2)
__device__ __half g_ah [MROWS*D_];      // fp16 agg out (layer 2)
__device__ __half g_h2h[MROWS*D_];      // fp16 h2 (layer 2)
__device__ __half g_hnh[MROWS*D_];      // fp16 ln out
__device__ float  g_xcat[MROWS*3*CIN_];
__device__ float2 g_Spart[B_*32*L_];
__device__ float  g_corr[B_*L_];
__device__ float  g_tcw [B_*TOPK_];
__device__ int    g_dly [B_*TOPK_];
__device__ float  g_cm  [B_*D_];
__device__ float  g_cb  [B_*CIN_];
// transposed (N,K) weights: tf32-rounded fp32 (pre-topk) / fp16 (post-topk)
__device__ float  g_wqkv[NL_*3*D_*D_];
__device__ float  g_bqkv[NL_*3*D_];
__device__ float  g_wto[NL_*D_*D_];     // l=0,1 used
__device__ float  g_wt1[NL_*DFF_*D_];   // l=0,1 used
__device__ float  g_wt2[NL_*D_*DFF_];   // l=0,1 used
__device__ float  g_wte[D_*192];
__device__ __half g_wtoh[D_*D_];        // layer-2 fp16 weights
__device__ __half g_wt1h[DFF_*D_];
__device__ __half g_wt2h[D_*DFF_];
__device__ __half g_wtph[128*D_];       // (64,512) padded to 128 rows

// ---------------- helpers ----------------
__device__ __forceinline__ float rtf32(float x) {
    uint32_t b = __float_as_uint(x);
    b = (b + 0x1000u) & 0xffffe000u;
    return __uint_as_float(b);
}
__device__ __forceinline__ float2 cadd(float2 a, float2 b){ return make_float2(a.x+b.x, a.y+b.y); }
__device__ __forceinline__ float2 csub(float2 a, float2 b){ return make_float2(a.x-b.x, a.y-b.y); }
__device__ __forceinline__ float2 cmul(float2 a, float2 b){ return make_float2(a.x*b.x-a.y*b.y, a.x*b.y+a.y*b.x); }
__device__ __forceinline__ float2 cneg(float2 a){ return make_float2(-a.x, -a.y); }

__device__ __forceinline__ uint32_t smem_u32(const void* p){
    uint32_t a;
    asm("{ .reg .u64 t; cvta.to.shared.u64 t, %1; cvt.u32.u64 %0, t; }" : "=r"(a) : "l"(p));
    return a;
}
__device__ __forceinline__ void cp16(uint32_t s, const void* g){
    asm volatile("cp.async.cg.shared.global [%0], [%1], 16;" :: "r"(s), "l"(g));
}
__device__ __forceinline__ void ldsm4(uint32_t* r, uint32_t addr){
    asm volatile("ldmatrix.sync.aligned.m8n8.x4.shared.b16 {%0,%1,%2,%3}, [%4];"
        : "=r"(r[0]),"=r"(r[1]),"=r"(r[2]),"=r"(r[3]) : "r"(addr));
}
#define MMA_TF32(d, a, b0, b1) \
    asm volatile("mma.sync.aligned.m16n8k8.row.col.f32.tf32.tf32.f32 " \
        "{%0,%1,%2,%3},{%4,%5,%6,%7},{%8,%9},{%0,%1,%2,%3};" \
        : "+f"((d)[0]),"+f"((d)[1]),"+f"((d)[2]),"+f"((d)[3]) \
        : "r"((a)[0]),"r"((a)[1]),"r"((a)[2]),"r"((a)[3]), "r"(b0),"r"(b1))
#define MMA_F16(d, a, b0, b1) \
    asm volatile("mma.sync.aligned.m16n8k16.row.col.f32.f16.f16.f32 " \
        "{%0,%1,%2,%3},{%4,%5,%6,%7},{%8,%9},{%0,%1,%2,%3};" \
        : "+f"((d)[0]),"+f"((d)[1]),"+f"((d)[2]),"+f"((d)[3]) \
        : "r"((a)[0]),"r"((a)[1]),"r"((a)[2]),"r"((a)[3]), "r"(b0),"r"(b1))

// ---------------- fused weight transposes: one launch, fp32 or fp16 dst ------
#define NJOBS 20
struct TJobs {
    const float* src[NJOBS];
    void*        dst[NJOBS];
    int K[NJOBS], N[NJOBS], Npad[NJOBS], tilesX[NJOBS], ishalf[NJOBS];
    int cum[NJOBS + 1];
};

__global__ void transpose_all_kernel(TJobs jb)
{
    __shared__ float t[32][33];
    int bid = blockIdx.x;
    int m = 0;
    while (bid >= jb.cum[m + 1]) m++;
    int lid = bid - jb.cum[m];
    int tX = jb.tilesX[m];
    int nb = (lid % tX) << 5, kb = (lid / tX) << 5;
    int K = jb.K[m], N = jb.N[m], Npad = jb.Npad[m];
    const float* in = jb.src[m];
    int x = threadIdx.x, y = threadIdx.y;     // 32 x 8
#pragma unroll
    for (int i = 0; i < 32; i += 8) {
        int k = kb + y + i, n = nb + x;
        t[y + i][x] = (k < K && n < N) ? in[(size_t)k * N + n] : 0.f;
    }
    __syncthreads();
    if (jb.ishalf[m]) {
        __half* out = (__half*)jb.dst[m];
#pragma unroll
        for (int i = 0; i < 32; i += 8) {
            int n = nb + y + i, k = kb + x;
            if (n < Npad && k < K) out[(size_t)n * K + k] = __float2half_rn(t[x][y + i]);
        }
    } else {
        float* out = (float*)jb.dst[m];
#pragma unroll
        for (int i = 0; i < 32; i += 8) {
            int n = nb + y + i, k = kb + x;
            if (n < Npad && k < K) out[(size_t)n * K + k] = rtf32(t[x][y + i]);
        }
    }
}

__global__ void biaspack_kernel(const float* __restrict__ bq, const float* __restrict__ bk,
                                const float* __restrict__ bv, float* __restrict__ out)
{
    int i = blockIdx.x*blockDim.x + threadIdx.x;
    if (i >= NL_*1536) return;
    int l = i / 1536, c = i % 1536;
    float v = (c < 512) ? bq[l*512 + c] : (c < 1024 ? bk[l*512 + c - 512] : bv[l*512 + c - 1024]);
    out[i] = v;
}

__global__ void xcat_kernel(const float* __restrict__ x, float* __restrict__ xc)
{
    int idx = blockIdx.x*blockDim.x + threadIdx.x;
    if (idx >= MROWS*192) return;
    int row = idx / 192, cc = idx % 192;
    int j = cc >> 6, c = cc & 63;
    int b = row >> 10, l = row & 1023;
    int ls = (l + j + 1023) & 1023;
    xc[idx] = rtf32(x[((((size_t)b)<<10) + ls)*64 + c]);
}

// ---------------- tf32 mma.sync GEMM (pre-topk path, bit-stable) -------------
template<int GELU, int ROUND>
__global__ __launch_bounds__(256, 2)
void tgemm(const float* __restrict__ A, const float* __restrict__ WT,
           const float* __restrict__ bias, float* __restrict__ Cf,
           __half* __restrict__ Ch, int K, int N)
{
    constexpr int STG_B = 32768;
    extern __shared__ float sm[];
    int tid = threadIdx.x;
    int lane = tid & 31, wid = tid >> 5;
    int wm = wid & 1, wn = wid >> 1;
    int bx = blockIdx.x, by = blockIdx.y;

    const float* Ab = A  + (size_t)(by * 128) * (size_t)K;
    const float* Bb = WT + (size_t)(bx * 128) * (size_t)K;
    const int nck = K >> 5;

    uint32_t sbase = smem_u32(sm);

    auto load = [&](int ck, int s){
        const float* ap = Ab + ck * 32;
        const float* bp = Bb + ck * 32;
        uint32_t st  = sbase + (uint32_t)s * STG_B;
        uint32_t st2 = st + 16384;
#pragma unroll
        for (int i = 0; i < 4; i++) {
            int t = tid + i*256;
            int row = t >> 3, ch = t & 7;
            uint32_t off = (uint32_t)((row << 7) + ((ch ^ (row & 7)) << 4));
            cp16(st + off, ap + (size_t)row*K + (ch << 2));
        }
#pragma unroll
        for (int i = 0; i < 4; i++) {
            int t = tid + i*256;
            int row = t >> 3, ch = t & 7;
            uint32_t off = (uint32_t)((row << 7) + ((ch ^ (row & 7)) << 4));
            cp16(st2 + off, bp + (size_t)row*K + (ch << 2));
        }
        asm volatile("cp.async.commit_group;" ::: "memory");
    };

    float acc[4][4][4];
#pragma unroll
    for (int mt = 0; mt < 4; mt++)
#pragma unroll
        for (int nt = 0; nt < 4; nt++)
#pragma unroll
            for (int j = 0; j < 4; j++) acc[mt][nt][j] = 0.f;

    int g = lane >> 3, r8 = lane & 7;
    int rA[4], rB[2];
#pragma unroll
    for (int mt = 0; mt < 4; mt++) rA[mt] = wm*64 + mt*16 + (g & 1)*8 + r8;
#pragma unroll
    for (int p = 0; p < 2; p++)    rB[p]  = wn*32 + p*16 + (g >> 1)*8 + r8;
    int chA = g >> 1;
    int chB = g & 1;

    load(0, 0); load(1, 1);
    int s = 0;

    for (int ck = 0; ck < nck; ck++) {
        asm volatile("cp.async.wait_group 1;" ::: "memory");
        __syncthreads();
        if (ck + 2 < nck) load(ck + 2, (s + 2 >= 3) ? s - 1 : s + 2);
        else asm volatile("cp.async.commit_group;" ::: "memory");

        uint32_t sa = sbase + (uint32_t)s * STG_B;
        uint32_t sb = sa + 16384;
#pragma unroll
        for (int kk = 0; kk < 4; kk++) {
            uint32_t af[4][4], bf[2][4];
#pragma unroll
            for (int mt = 0; mt < 4; mt++) {
                int ch = 2*kk + chA;
                uint32_t off = (uint32_t)((rA[mt] << 7) + ((ch ^ (rA[mt] & 7)) << 4));
                ldsm4(af[mt], sa + off);
            }
#pragma unroll
            for (int p = 0; p < 2; p++) {
                int ch = 2*kk + chB;
                uint32_t off = (uint32_t)((rB[p] << 7) + ((ch ^ (rB[p] & 7)) << 4));
                ldsm4(bf[p], sb + off);
            }
#pragma unroll
            for (int mt = 0; mt < 4; mt++)
#pragma unroll
                for (int nt = 0; nt < 4; nt++) {
                    int p = nt >> 1, q = nt & 1;
                    MMA_TF32(acc[mt][nt], af[mt], bf[p][2*q], bf[p][2*q+1]);
                }
        }
        s = (s == 2) ? 0 : s + 1;
    }

#pragma unroll
    for (int mt = 0; mt < 4; mt++) {
        int r0 = by*128 + wm*64 + mt*16 + (lane >> 2);
#pragma unroll
        for (int nt = 0; nt < 4; nt++) {
            int c = bx*128 + wn*32 + nt*8 + ((lane & 3) << 1);
            if (c < N) {
                float v0 = acc[mt][nt][0], v1 = acc[mt][nt][1];
                float v2 = acc[mt][nt][2], v3 = acc[mt][nt][3];
                if (bias != nullptr) {
                    float b0c = bias[c], b1c = bias[c+1];
                    v0 += b0c; v1 += b1c; v2 += b0c; v3 += b1c;
                }
                if (GELU) {
                    v0 = 0.5f*v0*(1.f + erff(v0*0.7071067811865475f));
                    v1 = 0.5f*v1*(1.f + erff(v1*0.7071067811865475f));
                    v2 = 0.5f*v2*(1.f + erff(v2*0.7071067811865475f));
                    v3 = 0.5f*v3*(1.f + erff(v3*0.7071067811865475f));
                }
                if (ROUND) { v0 = rtf32(v0); v1 = rtf32(v1); v2 = rtf32(v2); v3 = rtf32(v3); }
                if (Cf != nullptr) {
                    float* row0 = Cf + (size_t)r0 * (size_t)N;
                    float* row1 = row0 + ((size_t)N << 3);
                    *(float2*)(row0 + c) = make_float2(v0, v1);
                    *(float2*)(row1 + c) = make_float2(v2, v3);
                }
                if (Ch != nullptr) {
                    __half* hrow0 = Ch + (size_t)r0 * (size_t)N;
                    __half* hrow1 = hrow0 + ((size_t)N << 3);
                    *(__half2*)(hrow0 + c) = __halves2half2(__float2half_rn(v0), __float2half_rn(v1));
                    *(__half2*)(hrow1 + c) = __halves2half2(__float2half_rn(v2), __float2half_rn(v3));
                }
            }
        }
    }
}

// ---------------- fp16 mma.sync GEMM (post-last-topk path, 2x rate) ----------
template<int GELU>
__global__ __launch_bounds__(256, 2)
void tgemm_h(const __half* __restrict__ A, const __half* __restrict__ WT,
             const float* __restrict__ bias, float* __restrict__ Cf,
             __half* __restrict__ Ch, int K, int N)
{
    constexpr int STG_B = 32768;
    extern __shared__ float sm[];
    int tid = threadIdx.x;
    int lane = tid & 31, wid = tid >> 5;
    int wm = wid & 1, wn = wid >> 1;
    int bx = blockIdx.x, by = blockIdx.y;

    const __half* Ab = A  + (size_t)(by * 128) * (size_t)K;
    const __half* Bb = WT + (size_t)(bx * 128) * (size_t)K;
    const int nck = K >> 6;

    uint32_t sbase = smem_u32(sm);

    auto load = [&](int ck, int s){
        const __half* ap = Ab + ck * 64;
        const __half* bp = Bb + ck * 64;
        uint32_t st  = sbase + (uint32_t)s * STG_B;
        uint32_t st2 = st + 16384;
#pragma unroll
        for (int i = 0; i < 4; i++) {
            int t = tid + i*256;
            int row = t >> 3, ch = t & 7;
            uint32_t off = (uint32_t)((row << 7) + ((ch ^ (row & 7)) << 4));
            cp16(st + off, ap + (size_t)row*K + (ch << 3));
        }
#pragma unroll
        for (int i = 0; i < 4; i++) {
            int t = tid + i*256;
            int row = t >> 3, ch = t & 7;
            uint32_t off = (uint32_t)((row << 7) + ((ch ^ (row & 7)) << 4));
            cp16(st2 + off, bp + (size_t)row*K + (ch << 3));
        }
        asm volatile("cp.async.commit_group;" ::: "memory");
    };

    float acc[4][4][4];
#pragma unroll
    for (int mt = 0; mt < 4; mt++)
#pragma unroll
        for (int nt = 0; nt < 4; nt++)
#pragma unroll
            for (int j = 0; j < 4; j++) acc[mt][nt][j] = 0.f;

    int g = lane >> 3, r8 = lane & 7;
    int rA[4], rB[2];
#pragma unroll
    for (int mt = 0; mt < 4; mt++) rA[mt] = wm*64 + mt*16 + (g & 1)*8 + r8;
#pragma unroll
    for (int p = 0; p < 2; p++)    rB[p]  = wn*32 + p*16 + (g >> 1)*8 + r8;
    int chA = g >> 1;
    int chB = g & 1;

    load(0, 0); load(1, 1);
    int s = 0;

    for (int ck = 0; ck < nck; ck++) {
        asm volatile("cp.async.wait_group 1;" ::: "memory");
        __syncthreads();
        if (ck + 2 < nck) load(ck + 2, (s + 2 >= 3) ? s - 1 : s + 2);
        else asm volatile("cp.async.commit_group;" ::: "memory");

        uint32_t sa = sbase + (uint32_t)s * STG_B;
        uint32_t sb = sa + 16384;
#pragma unroll
        for (int kk = 0; kk < 4; kk++) {
            uint32_t af[4][4], bf[2][4];
#pragma unroll
            for (int mt = 0; mt < 4; mt++) {
                int ch = 2*kk + chA;
                uint32_t off = (uint32_t)((rA[mt] << 7) + ((ch ^ (rA[mt] & 7)) << 4));
                ldsm4(af[mt], sa + off);
            }
#pragma unroll
            for (int p = 0; p < 2; p++) {
                int ch = 2*kk + chB;
                uint32_t off = (uint32_t)((rB[p] << 7) + ((ch ^ (rB[p] & 7)) << 4));
                ldsm4(bf[p], sb + off);
            }
#pragma unroll
            for (int mt = 0; mt < 4; mt++)
#pragma unroll
                for (int nt = 0; nt < 4; nt++) {
                    int p = nt >> 1, q = nt & 1;
                    MMA_F16(acc[mt][nt], af[mt], bf[p][2*q], bf[p][2*q+1]);
                }
        }
        s = (s == 2) ? 0 : s + 1;
    }

#pragma unroll
    for (int mt = 0; mt < 4; mt++) {
        int r0 = by*128 + wm*64 + mt*16 + (lane >> 2);
#pragma unroll
        for (int nt = 0; nt < 4; nt++) {
            int c = bx*128 + wn*32 + nt*8 + ((lane & 3) << 1);
            if (c < N) {
                float v0 = acc[mt][nt][0], v1 = acc[mt][nt][1];
                float v2 = acc[mt][nt][2], v3 = acc[mt][nt][3];
                if (bias != nullptr) {
                    float b0c = bias[c], b1c = bias[c+1];
                    v0 += b0c; v1 += b1c; v2 += b0c; v3 += b1c;
                }
                if (GELU) {
                    v0 = 0.5f*v0*(1.f + erff(v0*0.7071067811865475f));
                    v1 = 0.5f*v1*(1.f + erff(v1*0.7071067811865475f));
                    v2 = 0.5f*v2*(1.f + erff(v2*0.7071067811865475f));
                    v3 = 0.5f*v3*(1.f + erff(v3*0.7071067811865475f));
                }
                if (Cf != nullptr) {
                    float* row0 = Cf + (size_t)r0 * (size_t)N;
                    float* row1 = row0 + ((size_t)N << 3);
                    *(float2*)(row0 + c) = make_float2(v0, v1);
                    *(float2*)(row1 + c) = make_float2(v2, v3);
                }
                if (Ch != nullptr) {
                    __half* hrow0 = Ch + (size_t)r0 * (size_t)N;
                    __half* hrow1 = hrow0 + ((size_t)N << 3);
                    *(__half2*)(hrow0 + c) = __halves2half2(__float2half_rn(v0), __float2half_rn(v1));
                    *(__half2*)(hrow1 + c) = __halves2half2(__float2half_rn(v2), __float2half_rn(v3));
                }
            }
        }
    }
}

// ---------------- radix-4 FFT (R15 proven 256-thread version) ----------------
template<int INV>
__device__ __forceinline__ float2 twget(const float2* tw, int e)
{
    float2 w = (e < 512) ? tw[e] : cneg(tw[e - 512]);
    if (INV) w.y = -w.y;
    return w;
}

template<int INV>
__device__ void fft1024_r4(float2* z, const float2* tw)
{
    int tid = threadIdx.x;
#pragma unroll
    for (int q = 1; q <= 256; q <<= 2) {
        int step = 256 / q;
        int j = tid & (q - 1);
        int base = ((tid & ~(q - 1)) << 2) + j;
        float2 x0 = z[base];
        float2 x1 = cmul(twget<INV>(tw, j*step),   z[base + q]);
        float2 x2 = cmul(twget<INV>(tw, 2*j*step), z[base + 2*q]);
        float2 x3 = cmul(twget<INV>(tw, 3*j*step), z[base + 3*q]);
        float2 t0 = cadd(x0, x2), t1 = csub(x0, x2);
        float2 t2 = cadd(x1, x3);
        float2 d  = csub(x1, x3);
        float2 t3 = INV ? make_float2(-d.y, d.x) : make_float2(d.y, -d.x);
        z[base]       = cadd(t0, t2);
        z[base + q]   = cadd(t1, t3);
        z[base + 2*q] = csub(t0, t2);
        z[base + 3*q] = csub(t1, t3);
        __syncthreads();
    }
}

__device__ __forceinline__ int r4rev(int t)
{
    int r = 0;
#pragma unroll
    for (int i = 0; i < 5; i++) { r = (r << 2) | (t & 3); t >>= 2; }
    return r;
}

// reads fused fp16 qkv buffer (row stride 1536): q at col d, k at col 512+d
__global__ __launch_bounds__(256)
void corr_fft_kernel(const __half* __restrict__ qkv, float2* __restrict__ Spart)
{
    __shared__ float2 z[1024];
    __shared__ float2 acc[1024];
    __shared__ float2 tw[512];
    int tid = threadIdx.x;
    int b = blockIdx.x, g = blockIdx.y;

    for (int i = tid; i < 512; i += 256) {
        float s, c;
        sincosf(-6.283185307179586f * (float)i / 1024.f, &s, &c);
        tw[i] = make_float2(c, s);
    }
    for (int i = tid; i < 1024; i += 256) acc[i] = make_float2(0.f, 0.f);
    __syncthreads();

    const __half* qb = qkv + (((size_t)b) << 10) * 1536;

    for (int dd = 0; dd < 16; dd++) {
        int d = (g << 4) + dd;
        for (int t = tid; t < 1024; t += 256) {
            const __half* rp = qb + (size_t)t * 1536 + d;
            z[r4rev(t)] = make_float2(__half2float(rp[0]), __half2float(rp[512]));
        }
        __syncthreads();
        fft1024_r4<0>(z, tw);
        for (int f = tid; f < 1024; f += 256) {
            float2 Zf = z[f];
            float2 Zm = z[(1024 - f) & 1023];
            float Qx = 0.5f*(Zf.x + Zm.x), Qy = 0.5f*(Zf.y - Zm.y);
            float Kx = 0.5f*(Zf.y + Zm.y), Ky = 0.5f*(Zm.x - Zf.x);
            float2 P = make_float2(Qx*Kx + Qy*Ky, Qy*Kx - Qx*Ky);
            acc[f] = cadd(acc[f], P);
        }
        __syncthreads();
    }
    float2* outp = Spart + ((((size_t)b) << 5) + g) * 1024;
    for (int f = tid; f < 1024; f += 256) outp[f] = acc[f];
}

__global__ __launch_bounds__(256)
void corr_ifft_kernel(const float2* __restrict__ Spart, float* __restrict__ corr)
{
    __shared__ float2 z[1024];
    __shared__ float2 tw[512];
    int tid = threadIdx.x;
    int b = blockIdx.x;

    for (int i = tid; i < 512; i += 256) {
        float s, c;
        sincosf(-6.283185307179586f * (float)i / 1024.f, &s, &c);
        tw[i] = make_float2(c, s);
    }
    __syncthreads();
    for (int t = tid; t < 1024; t += 256) {
        float2 s = make_float2(0.f, 0.f);
        const float2* sp = Spart + ((((size_t)b) << 5) * 1024) + t;
        for (int g2 = 0; g2 < 32; g2++) s = cadd(s, sp[(size_t)g2 << 10]);
        z[r4rev(t)] = s;
    }
    __syncthreads();
    fft1024_r4<1>(z, tw);
    const float scale = 1.f / (1024.f * 512.f);
    for (int t = tid; t < 1024; t += 256)
        corr[(b << 10) + t] = z[t].x * scale;
}

__global__ __launch_bounds__(256)
void topk_kernel(const float* __restrict__ corr, float* __restrict__ tcw, int* __restrict__ dly)
{
    int b = blockIdx.x, t = threadIdx.x;
    __shared__ float vals[1024];
    __shared__ float rv[256];
    __shared__ int   ri[256];
    __shared__ float wv[TOPK_];
    __shared__ int   wi[TOPK_];
    for (int i = t; i < 1024; i += 256) vals[i] = corr[(b << 10) + i];
    __syncthreads();
    for (int kk = 0; kk < TOPK_; kk++) {
        float bm = -INFINITY; int bi = 0x7fffffff;
        for (int i = t; i < 1024; i += 256) {
            float v = vals[i];
            if (v > bm || (v == bm && i < bi)) { bm = v; bi = i; }
        }
        rv[t] = bm; ri[t] = bi;
        __syncthreads();
        for (int s = 128; s > 0; s >>= 1) {
            if (t < s) {
                if (rv[t+s] > rv[t] || (rv[t+s] == rv[t] && ri[t+s] < ri[t])) {
                    rv[t] = rv[t+s]; ri[t] = ri[t+s];
                }
            }
            __syncthreads();
        }
        if (t == 0) { wv[kk] = rv[0]; wi[kk] = ri[0]; vals[ri[0]] = -INFINITY; }
        __syncthreads();
    }
    if (t == 0) {
        float m = wv[0];
        for (int kk = 1; kk < TOPK_; kk++) m = fmaxf(m, wv[kk]);
        float e[TOPK_], s = 0.f;
        for (int kk = 0; kk < TOPK_; kk++) { e[kk] = expf(wv[kk] - m); s += e[kk]; }
        float inv = 1.f / s;
        for (int kk = 0; kk < TOPK_; kk++) {
            tcw[b*TOPK_ + kk] = e[kk] * inv;
            dly[b*TOPK_ + kk] = wi[kk];
        }
    }
}

__global__ __launch_bounds__(128)
void agg_kernel(const __half* __restrict__ qkv, const float* __restrict__ tcw,
                const int* __restrict__ dly, float* __restrict__ outp,
                __half* __restrict__ outh)
{
    int bl = blockIdx.x;
    int b = bl >> 10, l = bl & 1023;
    __shared__ float w[TOPK_];
    __shared__ int   dd[TOPK_];
    if (threadIdx.x < TOPK_) {
        w[threadIdx.x]  = tcw[b*TOPK_ + threadIdx.x];
        dd[threadIdx.x] = dly[b*TOPK_ + threadIdx.x];
    }
    __syncthreads();
    int c = threadIdx.x << 2;
    float4 acc = make_float4(0.f, 0.f, 0.f, 0.f);
#pragma unroll
    for (int kk = 0; kk < TOPK_; kk++) {
        int row = (l + dd[kk]) & 1023;
        const __half* vp = qkv + ((((size_t)b) << 10) + row) * 1536 + 1024 + c;
        __half2 p0 = *(const __half2*)(vp);
        __half2 p1 = *(const __half2*)(vp + 2);
        float2 f0 = __half22float2(p0), f1 = __half22float2(p1);
        acc.x = fmaf(w[kk], f0.x, acc.x);
        acc.y = fmaf(w[kk], f0.y, acc.y);
        acc.z = fmaf(w[kk], f1.x, acc.z);
        acc.w = fmaf(w[kk], f1.y, acc.w);
    }
    acc.x = rtf32(acc.x); acc.y = rtf32(acc.y); acc.z = rtf32(acc.z); acc.w = rtf32(acc.w);
    if (outp != nullptr)
        *(float4*)(outp + (((size_t)bl) << 9) + c) = acc;
    if (outh != nullptr) {
        __half* op = outh + (((size_t)bl) << 9) + c;
        *(__half2*)(op)     = __halves2half2(__float2half_rn(acc.x), __float2half_rn(acc.y));
        *(__half2*)(op + 2) = __halves2half2(__float2half_rn(acc.z), __float2half_rn(acc.w));
    }
}

// decomp: in1 fp32 + in2 fp16 (tf32-rounded bits); fp32 out + optional fp16 shadow
__global__ __launch_bounds__(256)
void decomp_kernel(const float* __restrict__ in1, const __half* __restrict__ in2,
                   float* __restrict__ outp, __half* __restrict__ outh)
{
    __shared__ float s[152][64];
    int b = blockIdx.x, lt = blockIdx.y, dt = blockIdx.z;
    int l0 = lt << 7, d0 = dt << 6;
    int tid = threadIdx.x;
    for (int i = tid; i < 152*64; i += 256) {
        int r = i >> 6, d = i & 63;
        int l = l0 - 12 + r;
        l = l < 0 ? 0 : (l > 1023 ? 1023 : l);
        size_t gi = (((((size_t)b) << 10) + l) << 9) + d0 + d;
        s[r][d] = in1[gi] + __half2float(in2[gi]);
    }
    __syncthreads();
    int d = tid & 63, ch = tid >> 6;
    int lb = ch << 5;
    float sum = 0.f;
#pragma unroll
    for (int j = 0; j < 25; j++) sum += s[lb + j][d];
    for (int i = 0; i < 32; i++) {
        size_t gi = (((((size_t)b) << 10) + (l0 + lb + i)) << 9) + d0 + d;
        float v = rtf32(s[lb + 12 + i][d] - sum * (1.f/25.f));
        outp[gi] = v;
        if (outh != nullptr) outh[gi] = __float2half_rn(v);
        if (i != 31) sum += s[lb + 25 + i][d] - s[lb + i][d];
    }
}

__global__ __launch_bounds__(128)
void ln_kernel(const float* __restrict__ h, const float* __restrict__ gam,
               const float* __restrict__ bet, float* __restrict__ hn,
               __half* __restrict__ hnh)
{
    int row = blockIdx.x;
    int t = threadIdx.x;
    const float4 x = *(const float4*)(h + (((size_t)row) << 9) + (t << 2));
    float s1 = x.x + x.y + x.z + x.w;
    float s2 = x.x*x.x + x.y*x.y + x.z*x.z + x.w*x.w;
#pragma unroll
    for (int o = 16; o > 0; o >>= 1) {
        s1 += __shfl_xor_sync(0xffffffffu, s1, o);
        s2 += __shfl_xor_sync(0xffffffffu, s2, o);
    }
    __shared__ float a1[4], a2[4];
    if ((t & 31) == 0) { a1[t >> 5] = s1; a2[t >> 5] = s2; }
    __syncthreads();
    s1 = a1[0] + a1[1] + a1[2] + a1[3];
    s2 = a2[0] + a2[1] + a2[2] + a2[3];
    float mu  = s1 * (1.f/512.f);
    float var = s2 * (1.f/512.f) - mu*mu;
    float rs  = rsqrtf(var + 1e-5f);
    int c = t << 2;
    float4 o4;
    o4.x = rtf32((x.x - mu)*rs*gam[c+0] + bet[c+0]);
    o4.y = rtf32((x.y - mu)*rs*gam[c+1] + bet[c+1]);
    o4.z = rtf32((x.z - mu)*rs*gam[c+2] + bet[c+2]);
    o4.w = rtf32((x.w - mu)*rs*gam[c+3] + bet[c+3]);
    *(float4*)(hn + (((size_t)row) << 9) + c) = o4;
    __half* hp = hnh + (((size_t)row) << 9) + c;
    *(__half2*)(hp)     = __halves2half2(__float2half_rn(o4.x), __float2half_rn(o4.y));
    *(__half2*)(hp + 2) = __halves2half2(__float2half_rn(o4.z), __float2half_rn(o4.w));
}

__global__ __launch_bounds__(128)
void colmean_kernel(const float* __restrict__ hn, float* __restrict__ cm)
{
    int b = blockIdx.x;
    int d = blockIdx.y * 128 + threadIdx.x;
    float s = 0.f;
    const float* p = hn + ((((size_t)b) << 10) << 9) + d;
    for (int l = 0; l < 1024; l++) s += p[((size_t)l) << 9];
    cm[(b << 9) + d] = s * (1.f/1024.f);
}

__global__ __launch_bounds__(64)
void cbias_kernel(const float* __restrict__ cm, const float* __restrict__ pw,
                  float* __restrict__ cb)
{
    int b = blockIdx.x, n = threadIdx.x;
    float s = 0.f;
    for (int d2 = 0; d2 < 512; d2++)
        s = fmaf(cm[(b << 9) + d2], __half2float(__float2half_rn(pw[d2*64 + n])), s);
    cb[(b << 6) + n] = s;
}

__global__ void sub_kernel(float* __restrict__ outp, const float* __restrict__ cb)
{
    int i = blockIdx.x * blockDim.x + threadIdx.x;
    if (i >= MROWS*64) return;
    outp[i] -= cb[((i >> 16) << 6) + (i & 63)];
}

// ---------------- host launcher ----------------
extern "C" void kernel_launch(void* const* d_in, const int* in_sizes, int n_in,
                              void* d_out, int out_size)
{
    const float* x       = (const float*)d_in[0];
    const float* embed_w = (const float*)d_in[1];
    const float* wq = (const float*)d_in[2];  const float* bq = (const float*)d_in[3];
    const float* wk = (const float*)d_in[4];  const float* bk = (const float*)d_in[5];
    const float* wv = (const float*)d_in[6];  const float* bv = (const float*)d_in[7];
    const float* wo = (const float*)d_in[8];  const float* bo = (const float*)d_in[9];
    const float* w1 = (const float*)d_in[10]; const float* w2 = (const float*)d_in[11];
    const float* ln_g = (const float*)d_in[12]; const float* ln_b = (const float*)d_in[13];
    const float* pw = (const float*)d_in[14]; const float* pb = (const float*)d_in[15];
    float* outp = (float*)d_out;
    (void)in_sizes; (void)n_in; (void)out_size;

    float *h, *h2, *hn, *a, *ffn, *xc, *corr, *tcw, *cm, *cb, *bqkv;
    float *wqkv, *wto, *wt1, *wt2, *wte;
    __half *th, *qkvh, *ffnh, *ah, *h2h, *hnh, *wtoh, *wt1h, *wt2h, *wtph;
    float2* sp; int* dly;
    cudaGetSymbolAddress((void**)&h,    g_h);
    cudaGetSymbolAddress((void**)&h2,   g_h2);
    cudaGetSymbolAddress((void**)&hn,   g_hn);
    cudaGetSymbolAddress((void**)&a,    g_a);
    cudaGetSymbolAddress((void**)&th,   g_th);
    cudaGetSymbolAddress((void**)&qkvh, g_qkvh);
    cudaGetSymbolAddress((void**)&ffn,  g_ffn);
    cudaGetSymbolAddress((void**)&ffnh, g_ffnh);
    cudaGetSymbolAddress((void**)&ah,   g_ah);
    cudaGetSymbolAddress((void**)&h2h,  g_h2h);
    cudaGetSymbolAddress((void**)&hnh,  g_hnh);
    cudaGetSymbolAddress((void**)&xc,   g_xcat);
    cudaGetSymbolAddress((void**)&sp,   g_Spart);
    cudaGetSymbolAddress((void**)&corr, g_corr);
    cudaGetSymbolAddress((void**)&tcw,  g_tcw);
    cudaGetSymbolAddress((void**)&dly,  g_dly);
    cudaGetSymbolAddress((void**)&cm,   g_cm);
    cudaGetSymbolAddress((void**)&cb,   g_cb);
    cudaGetSymbolAddress((void**)&wqkv, g_wqkv);
    cudaGetSymbolAddress((void**)&bqkv, g_bqkv);
    cudaGetSymbolAddress((void**)&wto,  g_wto);
    cudaGetSymbolAddress((void**)&wt1,  g_wt1);
    cudaGetSymbolAddress((void**)&wt2,  g_wt2);
    cudaGetSymbolAddress((void**)&wte,  g_wte);
    cudaGetSymbolAddress((void**)&wtoh, g_wtoh);
    cudaGetSymbolAddress((void**)&wt1h, g_wt1h);
    cudaGetSymbolAddress((void**)&wt2h, g_wt2h);
    cudaGetSymbolAddress((void**)&wtph, g_wtph);

    const int SMB = 3 * 32768;
    cudaFuncSetAttribute(tgemm<0,1>, cudaFuncAttributeMaxDynamicSharedMemorySize, SMB);
    cudaFuncSetAttribute(tgemm<1,1>, cudaFuncAttributeMaxDynamicSharedMemorySize, SMB);
    cudaFuncSetAttribute(tgemm<0,0>, cudaFuncAttributeMaxDynamicSharedMemorySize, SMB);
    cudaFuncSetAttribute(tgemm_h<0>, cudaFuncAttributeMaxDynamicSharedMemorySize, SMB);
    cudaFuncSetAttribute(tgemm_h<1>, cudaFuncAttributeMaxDynamicSharedMemorySize, SMB);

    // ---- fused transpose job table ----
    TJobs jb;
    int nj = 0, cum = 0;
    auto addjob = [&](const float* src, void* dst, int K, int N, int Npad, int ishalf) {
        jb.src[nj] = src; jb.dst[nj] = dst;
        jb.K[nj] = K; jb.N[nj] = N; jb.Npad[nj] = Npad; jb.ishalf[nj] = ishalf;
        int tx = (Npad + 31) / 32, ty = (K + 31) / 32;
        jb.tilesX[nj] = tx;
        jb.cum[nj] = cum;
        cum += tx * ty;
        nj++;
    };
    addjob(embed_w, wte,  192, 512, 512, 0);
    addjob(pw,      wtph, 512, 64, 128, 1);
    for (int l = 0; l < NL_; l++) {
        float* wl = wqkv + (size_t)l*1536*512;
        addjob(wq + (size_t)l*D_*D_,   wl,                    512, 512, 512, 0);
        addjob(wk + (size_t)l*D_*D_,   wl + (size_t)512*512,  512, 512, 512, 0);
        addjob(wv + (size_t)l*D_*D_,   wl + (size_t)1024*512, 512, 512, 512, 0);
        if (l < NL_ - 1) {
            addjob(wo + (size_t)l*D_*D_,   wto + (size_t)l*D_*D_,   512, 512, 512, 0);
            addjob(w1 + (size_t)l*D_*DFF_, wt1 + (size_t)l*D_*DFF_, 512, 2048, 2048, 0);
            addjob(w2 + (size_t)l*D_*DFF_, wt2 + (size_t)l*D_*DFF_, 2048, 512, 512, 0);
        } else {
            addjob(wo + (size_t)l*D_*D_,   wtoh, 512, 512, 512, 1);
            addjob(w1 + (size_t)l*D_*DFF_, wt1h, 512, 2048, 2048, 1);
            addjob(w2 + (size_t)l*D_*DFF_, wt2h, 2048, 512, 512, 1);
        }
    }
    jb.cum[nj] = cum;
    transpose_all_kernel<<<cum, dim3(32, 8)>>>(jb);
    biaspack_kernel<<<(NL_*1536 + 255)/256, 256>>>(bq, bk, bv, bqkv);

    dim3 g512 (4,  MROWS/128);
    dim3 g1536(12, MROWS/128);
    dim3 g2048(16, MROWS/128);
    dim3 g64  (1,  MROWS/128);

    xcat_kernel<<<(MROWS*192 + 255)/256, 256>>>(x, xc);
    tgemm<0,1><<<g512, 256, SMB>>>(xc, wte, nullptr, h, nullptr, 192, 512);

    for (int l = 0; l < NL_; l++) {
        tgemm<0,0><<<g1536, 256, SMB>>>(h, wqkv + (size_t)l*1536*512, bqkv + l*1536,
                                        nullptr, qkvh, 512, 1536);

        corr_fft_kernel <<<dim3(B_, 32), 256>>>(qkvh, sp);
        corr_ifft_kernel<<<B_, 256>>>(sp, corr);
        topk_kernel     <<<B_, 256>>>(corr, tcw, dly);

        if (l < NL_ - 1) {
            // pre-topk path: bit-stable tf32 (t stored fp16 = identical bits post-rtf32)
            agg_kernel<<<MROWS, 128>>>(qkvh, tcw, dly, a, nullptr);
            tgemm<0,1><<<g512, 256, SMB>>>(a, wto + (size_t)l*D_*D_, bo + l*D_, nullptr, th, 512, 512);
            decomp_kernel<<<dim3(B_, 8, 8), 256>>>(h, th, h2, nullptr);
            tgemm<1,1><<<g2048, 256, SMB>>>(h2, wt1 + (size_t)l*D_*DFF_, nullptr, ffn, nullptr, 512, 2048);
            tgemm<0,1><<<g512,  256, SMB>>>(ffn, wt2 + (size_t)l*D_*DFF_, nullptr, nullptr, th, 2048, 512);
            decomp_kernel<<<dim3(B_, 8, 8), 256>>>(h2, th, h, nullptr);
        } else {
            // post-last-topk path: fp16 MMA
            agg_kernel<<<MROWS, 128>>>(qkvh, tcw, dly, nullptr, ah);
            tgemm_h<0><<<g512, 256, SMB>>>(ah, wtoh, bo + l*D_, nullptr, th, 512, 512);
            decomp_kernel<<<dim3(B_, 8, 8), 256>>>(h, th, h2, h2h);
            tgemm_h<1><<<g2048, 256, SMB>>>(h2h, wt1h, nullptr, nullptr, ffnh, 512, 2048);
            tgemm_h<0><<<g512,  256, SMB>>>(ffnh, wt2h, nullptr, nullptr, th, 2048, 512);
            decomp_kernel<<<dim3(B_, 8, 8), 256>>>(h2, th, h, nullptr);
        }
    }

    ln_kernel<<<MROWS, 128>>>(h, ln_g, ln_b, hn, hnh);
    colmean_kernel<<<dim3(B_, 4), 128>>>(hn, cm);
    cbias_kernel<<<B_, 64>>>(cm, pw, cb);
    tgemm_h<0><<<g64, 256, SMB>>>(hnh, wtph, pb, outp, nullptr, 512, 64);
    sub_kernel<<<(MROWS*64 + 255)/256, 256>>>(outp, cb);
}